// round 14
// baseline (speedup 1.0000x reference)
#include <cuda_runtime.h>
#include <cuda_bf16.h>
#include <math_constants.h>

// Problem shape (fixed by the dataset):
//   z_latents:  [128,32,32,64] f32  -> N = 131072 rows, D = 64
//   embeddings: [64,1024]      f32  -> D = 64, K = 1024
// Output: quantized_st (8388608 f32) then vq_loss (1 f32) -> 8388609 elements.

#define N_ROWS   131072
#define DIM      64
#define KCODES   1024
#define KCHUNK   64
#define THREADS  64
#define ROWS_CTA 256                      // 4 rows per thread (2 reg-resident, 2 smem-resident)
#define NBLOCKS  (N_ROWS / ROWS_CTA)      // 512

typedef unsigned long long u64;

__device__ double       g_partials[NBLOCKS];
__device__ unsigned int g_count;          // zero-init; last CTA resets to 0 each run

// ---------------- packed f32x2 helpers ----------------
__device__ __forceinline__ u64 pk2(float lo, float hi) {
    u64 r; asm("mov.b64 %0, {%1, %2};" : "=l"(r) : "f"(lo), "f"(hi)); return r;
}
__device__ __forceinline__ float2 u2f2(u64 v) {
    float2 f; asm("mov.b64 {%0, %1}, %2;" : "=f"(f.x), "=f"(f.y) : "l"(v)); return f;
}
__device__ __forceinline__ u64 swp(u64 v) {
    u64 r;
    asm("{\n\t.reg .b32 lo, hi;\n\tmov.b64 {lo,hi}, %1;\n\tmov.b64 %0, {hi,lo};\n\t}"
        : "=l"(r) : "l"(v));
    return r;
}
__device__ __forceinline__ u64 ffma2(u64 a, u64 b, u64 c) {
    u64 d; asm("fma.rn.f32x2 %0, %1, %2, %3;" : "=l"(d) : "l"(a), "l"(b), "l"(c)); return d;
}
__device__ __forceinline__ u64 add2(u64 a, u64 b) {
    u64 d; asm("add.rn.f32x2 %0, %1, %2;" : "=l"(d) : "l"(a), "l"(b)); return d;
}

// ---------------- smem layout (floats) ----------------
//   zq  : [DIM][THREADS] u64 pairs (rows 2,3 of each thread)   8192 f (32 KB)
//   cbs : [DIM][KCHUNK]  codebook chunk, k-major               4096 f (16 KB)
//   ses : [KCHUNK]                                               64 f
//   red : 64 doubles (CTA + last-CTA reductions)                128 f
#define ZQ_OFF   0
#define CBS_OFF  (DIM * THREADS * 2)
#define SES_OFF  (CBS_OFF + DIM * KCHUNK)
#define RED_OFF  (SES_OFF + KCHUNK)
#define SMEM_BYTES ((RED_OFF + 2 * THREADS) * 4)

__global__ void __launch_bounds__(THREADS, 4)
vq_main(const float* __restrict__ z,
        const float* __restrict__ emb,
        float* __restrict__ out)
{
    extern __shared__ float smem[];
    u64*    zq  = (u64*)smem;
    float*  cbs = smem + CBS_OFF;
    float*  ses = smem + SES_OFF;
    double* red = (double*)(smem + RED_OFF);
    __shared__ int s_last;

    const int b = blockIdx.x;
    const int t = threadIdx.x;
    const float* zg = z + (size_t)b * ROWS_CTA * DIM;

    // rows owned by this thread: a=2t, b2=2t+1 (registers, packed),
    //                            c=128+2t, d2=129+2t (smem, packed pairs)
    u64   zp[DIM];
    float sza = 0.0f, szb = 0.0f, szc = 0.0f, szd = 0.0f;
    {
        const float4* pa = (const float4*)(zg + (size_t)(2 * t)     * DIM);
        const float4* pb = (const float4*)(zg + (size_t)(2 * t + 1) * DIM);
        #pragma unroll
        for (int j = 0; j < 16; ++j) {
            float4 va = pa[j], vb = pb[j];
            zp[4*j+0] = pk2(va.x, vb.x);
            zp[4*j+1] = pk2(va.y, vb.y);
            zp[4*j+2] = pk2(va.z, vb.z);
            zp[4*j+3] = pk2(va.w, vb.w);
            sza = __fadd_rn(sza, __fmul_rn(va.x, va.x));
            sza = __fadd_rn(sza, __fmul_rn(va.y, va.y));
            sza = __fadd_rn(sza, __fmul_rn(va.z, va.z));
            sza = __fadd_rn(sza, __fmul_rn(va.w, va.w));
            szb = __fadd_rn(szb, __fmul_rn(vb.x, vb.x));
            szb = __fadd_rn(szb, __fmul_rn(vb.y, vb.y));
            szb = __fadd_rn(szb, __fmul_rn(vb.z, vb.z));
            szb = __fadd_rn(szb, __fmul_rn(vb.w, vb.w));
        }
        const float4* pc = (const float4*)(zg + (size_t)(128 + 2 * t) * DIM);
        const float4* pd = (const float4*)(zg + (size_t)(129 + 2 * t) * DIM);
        #pragma unroll
        for (int j = 0; j < 16; ++j) {
            float4 vc = pc[j], vd = pd[j];
            zq[(4*j+0) * THREADS + t] = pk2(vc.x, vd.x);
            zq[(4*j+1) * THREADS + t] = pk2(vc.y, vd.y);
            zq[(4*j+2) * THREADS + t] = pk2(vc.z, vd.z);
            zq[(4*j+3) * THREADS + t] = pk2(vc.w, vd.w);
            szc = __fadd_rn(szc, __fmul_rn(vc.x, vc.x));
            szc = __fadd_rn(szc, __fmul_rn(vc.y, vc.y));
            szc = __fadd_rn(szc, __fmul_rn(vc.z, vc.z));
            szc = __fadd_rn(szc, __fmul_rn(vc.w, vc.w));
            szd = __fadd_rn(szd, __fmul_rn(vd.x, vd.x));
            szd = __fadd_rn(szd, __fmul_rn(vd.y, vd.y));
            szd = __fadd_rn(szd, __fmul_rn(vd.z, vd.z));
            szd = __fadd_rn(szd, __fmul_rn(vd.w, vd.w));
        }
    }
    // zq is thread-private: no sync needed for it.

    const u64 M2   = pk2(-2.0f, -2.0f);
    const u64 szab = pk2(sza, szb), szba = pk2(szb, sza);
    const u64 szcd = pk2(szc, szd), szdc = pk2(szd, szc);

    float best0 = CUDART_INF_F, best1 = CUDART_INF_F;
    float best2 = CUDART_INF_F, best3 = CUDART_INF_F;
    int   bi0 = 0, bi1 = 0, bi2 = 0, bi3 = 0;

    for (int k0 = 0; k0 < KCODES; k0 += KCHUNK) {
        __syncthreads();
        // stage codebook chunk cbs[d][kc] (coalesced float4, L2-resident source)
        {
            float4* dst4 = (float4*)cbs;
            #pragma unroll
            for (int i = 0; i < (DIM * KCHUNK / 4) / THREADS; ++i) {   // 16
                int idx = i * THREADS + t;
                int d   = idx >> 4;             // 16 float4 per d-row
                int kc4 = idx & 15;
                dst4[idx] = *(const float4*)(emb + (size_t)d * KCODES + k0 + 4 * kc4);
            }
        }
        __syncthreads();
        // per-code squared norms: sequential ascending d (bit-matches reference)
        {
            float s = 0.0f;
            #pragma unroll
            for (int d = 0; d < DIM; ++d) {
                float v = cbs[d * KCHUNK + t];
                s = __fadd_rn(s, __fmul_rn(v, v));
            }
            ses[t] = s;
        }
        __syncthreads();

        const ulonglong2* cb2  = (const ulonglong2*)cbs;   // 16 per d-row
        const u64*        sesp = (const u64*)ses;

        #pragma unroll 1                     // keep hot loop I$-resident (~26 KB)
        for (int kg = 0; kg < KCHUNK; kg += 8) {
            const ulonglong2* cbk = cb2 + (kg >> 2);
            u64 abF[4] = {0,0,0,0}, abS[4] = {0,0,0,0};
            u64 cdF[4] = {0,0,0,0}, cdS[4] = {0,0,0,0};
            #pragma unroll
            for (int d = 0; d < DIM; ++d) {
                ulonglong2 e01 = cbk[d * 16];        // codes kg..kg+3 (broadcast LDS.128)
                ulonglong2 e23 = cbk[d * 16 + 1];    // codes kg+4..kg+7
                u64 zzA = zp[d];
                u64 zzB = swp(zzA);
                u64 zzC = zq[d * THREADS + t];       // conflict-free LDS.64
                u64 zzD = swp(zzC);
                abF[0] = ffma2(zzA, e01.x, abF[0]);  abS[0] = ffma2(zzB, e01.x, abS[0]);
                abF[1] = ffma2(zzA, e01.y, abF[1]);  abS[1] = ffma2(zzB, e01.y, abS[1]);
                abF[2] = ffma2(zzA, e23.x, abF[2]);  abS[2] = ffma2(zzB, e23.x, abS[2]);
                abF[3] = ffma2(zzA, e23.y, abF[3]);  abS[3] = ffma2(zzB, e23.y, abS[3]);
                cdF[0] = ffma2(zzC, e01.x, cdF[0]);  cdS[0] = ffma2(zzD, e01.x, cdS[0]);
                cdF[1] = ffma2(zzC, e01.y, cdF[1]);  cdS[1] = ffma2(zzD, e01.y, cdS[1]);
                cdF[2] = ffma2(zzC, e23.x, cdF[2]);  cdS[2] = ffma2(zzD, e23.x, cdS[2]);
                cdF[3] = ffma2(zzC, e23.y, cdF[3]);  cdS[3] = ffma2(zzD, e23.y, cdS[3]);
            }
            // dist = fma(-2, dot, sz) + se  (single rounding, == (sz-2*dot)+se)
            #pragma unroll
            for (int q = 0; q < 4; ++q) {
                u64 sep = sesp[(kg >> 1) + q];       // (se_even, se_odd) broadcast LDS.64
                float2 fab = u2f2(add2(ffma2(M2, abF[q], szab), sep));
                float2 sab = u2f2(add2(ffma2(M2, abS[q], szba), sep));
                float2 fcd = u2f2(add2(ffma2(M2, cdF[q], szcd), sep));
                float2 scd = u2f2(add2(ffma2(M2, cdS[q], szdc), sep));
                int kE = k0 + kg + 2 * q, kO = kE + 1;
                // ascending code order per row, strict < => first occurrence
                if (fab.x < best0) { best0 = fab.x; bi0 = kE; }
                if (sab.y < best0) { best0 = sab.y; bi0 = kO; }
                if (sab.x < best1) { best1 = sab.x; bi1 = kE; }
                if (fab.y < best1) { best1 = fab.y; bi1 = kO; }
                if (fcd.x < best2) { best2 = fcd.x; bi2 = kE; }
                if (scd.y < best2) { best2 = scd.y; bi2 = kO; }
                if (scd.x < best3) { best3 = scd.x; bi3 = kE; }
                if (fcd.y < best3) { best3 = fcd.y; bi3 = kO; }
            }
        }
    }

    // ---- gather chosen codes (emb L2-resident), ST output, loss partial ----
    double lsum = 0.0;
    const size_t B = (size_t)b * ROWS_CTA;
    {
        float4* oa = (float4*)(out + (B + 2 * t)     * DIM);
        float4* ob = (float4*)(out + (B + 2 * t + 1) * DIM);
        #pragma unroll
        for (int j = 0; j < 16; ++j) {
            float4 va, vb;
            #pragma unroll
            for (int c = 0; c < 4; ++c) {
                int d = 4 * j + c;
                float2 zz = u2f2(zp[d]);
                float qa = __ldg(emb + (size_t)d * KCODES + bi0);
                float qb = __ldg(emb + (size_t)d * KCODES + bi1);
                float ea = __fsub_rn(qa, zz.x);  (&va.x)[c] = __fadd_rn(zz.x, ea);
                float eb = __fsub_rn(qb, zz.y);  (&vb.x)[c] = __fadd_rn(zz.y, eb);
                lsum += (double)__fmul_rn(ea, ea) + (double)__fmul_rn(eb, eb);
            }
            oa[j] = va;  ob[j] = vb;
        }
        float4* oc = (float4*)(out + (B + 128 + 2 * t) * DIM);
        float4* od = (float4*)(out + (B + 129 + 2 * t) * DIM);
        #pragma unroll
        for (int j = 0; j < 16; ++j) {
            float4 vc, vd;
            #pragma unroll
            for (int c = 0; c < 4; ++c) {
                int d = 4 * j + c;
                float2 zz = u2f2(zq[d * THREADS + t]);
                float qc = __ldg(emb + (size_t)d * KCODES + bi2);
                float qd = __ldg(emb + (size_t)d * KCODES + bi3);
                float ec = __fsub_rn(qc, zz.x);  (&vc.x)[c] = __fadd_rn(zz.x, ec);
                float ed = __fsub_rn(qd, zz.y);  (&vd.x)[c] = __fadd_rn(zz.y, ed);
                lsum += (double)__fmul_rn(ec, ec) + (double)__fmul_rn(ed, ed);
            }
            oc[j] = vc;  od[j] = vd;
        }
    }

    // deterministic CTA reduction (2 warps)
    #pragma unroll
    for (int o = 16; o > 0; o >>= 1)
        lsum += __shfl_down_sync(0xffffffffu, lsum, o);
    if ((t & 31) == 0) red[t >> 5] = lsum;
    __syncthreads();
    if (t == 0) {
        g_partials[b] = red[0] + red[1];
        __threadfence();
        unsigned v = atomicAdd(&g_count, 1);
        s_last = (v == NBLOCKS - 1) ? 1 : 0;
    }
    __syncthreads();

    // last CTA: fixed-order reduction of all partials -> vq_loss
    if (s_last) {
        __threadfence();
        double s = 0.0;
        #pragma unroll
        for (int i = 0; i < NBLOCKS / THREADS; ++i)            // 8 each, fixed order
            s += __ldcg(&g_partials[t * (NBLOCKS / THREADS) + i]);
        red[t] = s;
        __syncthreads();
        #pragma unroll
        for (int stp = 32; stp > 0; stp >>= 1) {
            if (t < stp) red[t] += red[t + stp];
            __syncthreads();
        }
        if (t == 0) {
            float L = (float)(red[0] / (double)(N_ROWS * DIM));
            out[N_ROWS * DIM] = __fadd_rn(L, __fmul_rn(0.25f, L));
            g_count = 0;                                       // reset for next replay
        }
    }
}

extern "C" void kernel_launch(void* const* d_in, const int* in_sizes, int n_in,
                              void* d_out, int out_size) {
    const float* z   = (const float*)d_in[0];
    const float* emb = (const float*)d_in[1];
    float* out = (float*)d_out;

    (void)in_sizes; (void)n_in; (void)out_size;

    cudaFuncSetAttribute(vq_main, cudaFuncAttributeMaxDynamicSharedMemorySize, SMEM_BYTES);

    vq_main<<<NBLOCKS, THREADS, SMEM_BYTES>>>(z, emb, out);
}

// round 16
// speedup vs baseline: 1.3062x; 1.3062x over previous
#include <cuda_runtime.h>
#include <cuda_bf16.h>
#include <math_constants.h>
#include <cstdint>

// Problem shape (fixed by the dataset):
//   z_latents:  [128,32,32,64] f32  -> N = 131072 rows, D = 64
//   embeddings: [64,1024]      f32  -> D = 64, K = 1024
// Output: quantized_st (8388608 f32) then vq_loss (1 f32) -> 8388609 elements.

#define N_ROWS     131072
#define DIM        64
#define KCODES     1024
#define KCHUNK     128
#define NCHUNK     (KCODES / KCHUNK)       // 8
#define THREADS    128
#define BIG_TILES  384
#define BIG_ROWS   256
#define SMALL_TILES 256
#define SMALL_ROWS 128
#define NBLOCKS    (BIG_TILES + SMALL_TILES)   // 640

typedef unsigned long long u64;

__device__ float        g_cbT[KCODES * DIM];   // codebook transposed [K][D]
__device__ double       g_partials[NBLOCKS];
__device__ unsigned int g_count;

// ---------------- packed f32x2 helpers ----------------
__device__ __forceinline__ u64 pk2(float lo, float hi) {
    u64 r; asm("mov.b64 %0, {%1, %2};" : "=l"(r) : "f"(lo), "f"(hi)); return r;
}
__device__ __forceinline__ float2 u2f2(u64 v) {
    float2 f; asm("mov.b64 {%0, %1}, %2;" : "=f"(f.x), "=f"(f.y) : "l"(v)); return f;
}
__device__ __forceinline__ u64 ffma2(u64 a, u64 b, u64 c) {
    u64 d; asm("fma.rn.f32x2 %0, %1, %2, %3;" : "=l"(d) : "l"(a), "l"(b), "l"(c)); return d;
}
__device__ __forceinline__ u64 add2(u64 a, u64 b) {
    u64 d; asm("add.rn.f32x2 %0, %1, %2;" : "=l"(d) : "l"(a), "l"(b)); return d;
}

// ---------------- cp.async helpers ----------------
__device__ __forceinline__ void cpa16(unsigned int dst, const void* src) {
    asm volatile("cp.async.ca.shared.global [%0], [%1], 16;" :: "r"(dst), "l"(src));
}
__device__ __forceinline__ void cpa_commit() {
    asm volatile("cp.async.commit_group;");
}
template <int N>
__device__ __forceinline__ void cpa_wait() {
    asm volatile("cp.async.wait_group %0;" :: "n"(N));
}

// ---------------- init: transpose codebook + reset counter ----------------
__global__ void vq_init(const float* __restrict__ emb) {
    int k = blockIdx.x * 64 + threadIdx.x;        // grid 16 x 64
    #pragma unroll
    for (int j = 0; j < DIM / 4; ++j) {
        float4 v;
        v.x = emb[(4 * j + 0) * KCODES + k];
        v.y = emb[(4 * j + 1) * KCODES + k];
        v.z = emb[(4 * j + 2) * KCODES + k];
        v.w = emb[(4 * j + 3) * KCODES + k];
        ((float4*)(g_cbT + (size_t)k * DIM))[j] = v;
    }
    if (blockIdx.x == 0 && threadIdx.x == 0) g_count = 0;
}

// ---------------- main ----------------
// dynamic smem (floats):
//   cbs : 2 x [DIM][KCHUNK]  double-buffered codebook chunk  16384 f (64 KB)
//   ses : [KCHUNK]                                             128 f
//   red : 128 doubles                                          256 f
#define CBS_OFF  0
#define SES_OFF  (2 * DIM * KCHUNK)
#define RED_OFF  (SES_OFF + KCHUNK)
#define SMEM_BYTES ((RED_OFF + 256) * 4)

__global__ void __launch_bounds__(THREADS, 2)
vq_main(const float* __restrict__ z,
        const float* __restrict__ emb,
        float* __restrict__ out)
{
    extern __shared__ float smem[];
    float*  cbs = smem + CBS_OFF;
    float*  ses = smem + SES_OFF;
    double* red = (double*)(smem + RED_OFF);
    __shared__ int s_last;

    const int b = blockIdx.x;
    const int t = threadIdx.x;

    // tile geometry: big tiles first (scheduled first), small tiles fill the tail
    size_t row0;  int nrows;
    if (b < BIG_TILES) { row0 = (size_t)b * BIG_ROWS;  nrows = BIG_ROWS; }
    else { row0 = (size_t)BIG_TILES * BIG_ROWS + (size_t)(b - BIG_TILES) * SMALL_ROWS;
           nrows = SMALL_ROWS; }
    const bool active = (2 * t + 1) < nrows;

    // ---- prologue: prefetch chunks 0 and 1 via cp.async ----
    {
        #pragma unroll
        for (int c = 0; c < 2; ++c) {
            #pragma unroll
            for (int i = 0; i < 16; ++i) {
                int idx = i * THREADS + t;                   // float4 index in chunk
                int d   = idx >> 5;                          // 32 float4 per d-row
                int kc4 = idx & 31;
                unsigned int dst = (unsigned int)__cvta_generic_to_shared(
                                       cbs + c * (DIM * KCHUNK) + 4 * idx);
                cpa16(dst, emb + (size_t)d * KCODES + c * KCHUNK + 4 * kc4);
            }
            cpa_commit();
        }
    }

    // ---- load this thread's two z rows into registers ----
    float zr0[DIM], zr1[DIM];
    float sz0 = 0.0f, sz1 = 0.0f;
    if (active) {
        const float4* p0 = (const float4*)(z + (row0 + 2 * t)     * DIM);
        const float4* p1 = (const float4*)(z + (row0 + 2 * t + 1) * DIM);
        #pragma unroll
        for (int j = 0; j < DIM / 4; ++j) {
            float4 a = p0[j];
            zr0[4*j+0] = a.x; zr0[4*j+1] = a.y; zr0[4*j+2] = a.z; zr0[4*j+3] = a.w;
            float4 c = p1[j];
            zr1[4*j+0] = c.x; zr1[4*j+1] = c.y; zr1[4*j+2] = c.z; zr1[4*j+3] = c.w;
        }
        // s_z: square then add, ascending d (matches reference)
        #pragma unroll
        for (int d = 0; d < DIM; ++d) {
            sz0 = __fadd_rn(sz0, __fmul_rn(zr0[d], zr0[d]));
            sz1 = __fadd_rn(sz1, __fmul_rn(zr1[d], zr1[d]));
        }
    }

    const u64 M2   = pk2(-2.0f, -2.0f);
    const u64 szab = pk2(sz0, sz1), szba = pk2(sz1, sz0);

    float best0 = CUDART_INF_F, best1 = CUDART_INF_F;
    int   bi0 = 0, bi1 = 0;

    #pragma unroll 1
    for (int c = 0; c < NCHUNK; ++c) {
        // wait for chunk c (at most one newer group — chunk c+1 — may remain)
        if (c + 1 < NCHUNK) cpa_wait<1>(); else cpa_wait<0>();
        __syncthreads();

        float* cur = cbs + (c & 1) * (DIM * KCHUNK);

        // per-code squared norms from the staged chunk: sequential ascending d
        {
            float s = 0.0f;
            #pragma unroll
            for (int d = 0; d < DIM; ++d) {
                float v = cur[d * KCHUNK + t];
                s = __fadd_rn(s, __fmul_rn(v, v));
            }
            ses[t] = s;
        }
        __syncthreads();

        if (active) {
            const ulonglong2* cb2  = (const ulonglong2*)cur;   // 32 per d-row
            const u64*        sesp = (const u64*)ses;
            const int         k0   = c * KCHUNK;

            #pragma unroll 1                     // keep hot loop I$-resident
            for (int kg = 0; kg < KCHUNK; kg += 8) {
                const ulonglong2* cbk = cb2 + (kg >> 2);
                // aF[q]: (z0,z1) x (e_{2q},e_{2q+1}); aS[q]: (z1,z0) x same
                u64 aF[4] = {0,0,0,0}, aS[4] = {0,0,0,0};
                #pragma unroll
                for (int d = 0; d < DIM; ++d) {
                    ulonglong2 e01 = cbk[d * 32];        // codes kg..kg+3 (broadcast)
                    ulonglong2 e23 = cbk[d * 32 + 1];    // codes kg+4..kg+7
                    u64 zzA = pk2(zr0[d], zr1[d]);
                    u64 zzB = pk2(zr1[d], zr0[d]);
                    aF[0] = ffma2(zzA, e01.x, aF[0]);  aS[0] = ffma2(zzB, e01.x, aS[0]);
                    aF[1] = ffma2(zzA, e01.y, aF[1]);  aS[1] = ffma2(zzB, e01.y, aS[1]);
                    aF[2] = ffma2(zzA, e23.x, aF[2]);  aS[2] = ffma2(zzB, e23.x, aS[2]);
                    aF[3] = ffma2(zzA, e23.y, aF[3]);  aS[3] = ffma2(zzB, e23.y, aS[3]);
                }
                // dist = fma(-2, dot, sz) + se  (single rounding == (sz-2*dot)+se)
                #pragma unroll
                for (int q = 0; q < 4; ++q) {
                    u64 sep = sesp[(kg >> 1) + q];       // (se_even, se_odd)
                    float2 fab = u2f2(add2(ffma2(M2, aF[q], szab), sep));
                    float2 sab = u2f2(add2(ffma2(M2, aS[q], szba), sep));
                    int kE = k0 + kg + 2 * q, kO = kE + 1;
                    // ascending code order per row, strict < => first occurrence
                    if (fab.x < best0) { best0 = fab.x; bi0 = kE; }
                    if (sab.y < best0) { best0 = sab.y; bi0 = kO; }
                    if (sab.x < best1) { best1 = sab.x; bi1 = kE; }
                    if (fab.y < best1) { best1 = fab.y; bi1 = kO; }
                }
            }
        }
        __syncthreads();

        // prefetch chunk c+2 into the buffer we just finished with
        if (c + 2 < NCHUNK) {
            #pragma unroll
            for (int i = 0; i < 16; ++i) {
                int idx = i * THREADS + t;
                int d   = idx >> 5;
                int kc4 = idx & 31;
                unsigned int dst = (unsigned int)__cvta_generic_to_shared(
                                       cbs + (c & 1) * (DIM * KCHUNK) + 4 * idx);
                cpa16(dst, emb + (size_t)d * KCODES + (c + 2) * KCHUNK + 4 * kc4);
            }
            cpa_commit();
        }
    }

    // ---- gather chosen codes from transposed codebook (contiguous),
    //      straight-through output, loss partial ----
    double lsum = 0.0;
    if (active) {
        const float4* qa = (const float4*)(g_cbT + (size_t)bi0 * DIM);
        const float4* qb = (const float4*)(g_cbT + (size_t)bi1 * DIM);
        float4* oa = (float4*)(out + (row0 + 2 * t)     * DIM);
        float4* ob = (float4*)(out + (row0 + 2 * t + 1) * DIM);
        #pragma unroll
        for (int j = 0; j < DIM / 4; ++j) {
            float4 q4a = qa[j], q4b = qb[j];
            float4 va, vb;
            #pragma unroll
            for (int cc = 0; cc < 4; ++cc) {
                int d = 4 * j + cc;
                float ea = __fsub_rn((&q4a.x)[cc], zr0[d]);
                float eb = __fsub_rn((&q4b.x)[cc], zr1[d]);
                (&va.x)[cc] = __fadd_rn(zr0[d], ea);
                (&vb.x)[cc] = __fadd_rn(zr1[d], eb);
                lsum += (double)__fmul_rn(ea, ea) + (double)__fmul_rn(eb, eb);
            }
            oa[j] = va;  ob[j] = vb;
        }
    }

    // deterministic CTA reduction (4 warps)
    #pragma unroll
    for (int o = 16; o > 0; o >>= 1)
        lsum += __shfl_down_sync(0xffffffffu, lsum, o);
    if ((t & 31) == 0) red[t >> 5] = lsum;
    __syncthreads();
    if (t == 0) {
        g_partials[b] = red[0] + red[1] + red[2] + red[3];
        __threadfence();
        unsigned v = atomicAdd(&g_count, 1);
        s_last = (v == NBLOCKS - 1) ? 1 : 0;
    }
    __syncthreads();

    // last CTA: fixed-order reduction of all partials -> vq_loss
    if (s_last) {
        __threadfence();
        double s = 0.0;
        #pragma unroll
        for (int i = 0; i < NBLOCKS / THREADS; ++i)      // 5 each, fixed order
            s += __ldcg(&g_partials[t * (NBLOCKS / THREADS) + i]);
        red[t] = s;
        __syncthreads();
        #pragma unroll
        for (int stp = 64; stp > 0; stp >>= 1) {
            if (t < stp) red[t] += red[t + stp];
            __syncthreads();
        }
        if (t == 0) {
            float L = (float)(red[0] / (double)(N_ROWS * DIM));
            // vq_loss = embedding_loss + 0.25 * commitment_loss (numerically equal)
            out[N_ROWS * DIM] = __fadd_rn(L, __fmul_rn(0.25f, L));
        }
    }
}

extern "C" void kernel_launch(void* const* d_in, const int* in_sizes, int n_in,
                              void* d_out, int out_size) {
    const float* z   = (const float*)d_in[0];
    const float* emb = (const float*)d_in[1];
    float* out = (float*)d_out;

    (void)in_sizes; (void)n_in; (void)out_size;

    cudaFuncSetAttribute(vq_main, cudaFuncAttributeMaxDynamicSharedMemorySize, SMEM_BYTES);

    vq_init<<<KCODES / 64, 64>>>(emb);
    vq_main<<<NBLOCKS, THREADS, SMEM_BYTES>>>(z, emb, out);
}

// round 17
// speedup vs baseline: 1.5876x; 1.2155x over previous
#include <cuda_runtime.h>
#include <cuda_bf16.h>
#include <math_constants.h>
#include <cstdint>

// Problem shape (fixed by the dataset):
//   z_latents:  [128,32,32,64] f32  -> N = 131072 rows, D = 64
//   embeddings: [64,1024]      f32  -> D = 64, K = 1024
// Output: quantized_st (8388608 f32) then vq_loss (1 f32) -> 8388609 elements.

#define N_ROWS     131072
#define DIM        64
#define KCODES     1024
#define KCHUNK     128
#define NCHUNK     (KCODES / KCHUNK)       // 8
#define THREADS    128
#define ROWS_CTA   256                     // 2 rows per thread
#define NBLOCKS    (N_ROWS / ROWS_CTA)     // 512

typedef unsigned long long u64;

__device__ float        g_cbT[KCODES * DIM];   // codebook transposed [K][D]
__device__ double       g_partials[NBLOCKS];
__device__ unsigned int g_count;

// ---------------- packed f32x2 helpers ----------------
__device__ __forceinline__ u64 pk2(float lo, float hi) {
    u64 r; asm("mov.b64 %0, {%1, %2};" : "=l"(r) : "f"(lo), "f"(hi)); return r;
}
__device__ __forceinline__ float2 u2f2(u64 v) {
    float2 f; asm("mov.b64 {%0, %1}, %2;" : "=f"(f.x), "=f"(f.y) : "l"(v)); return f;
}
__device__ __forceinline__ u64 ffma2(u64 a, u64 b, u64 c) {
    u64 d; asm("fma.rn.f32x2 %0, %1, %2, %3;" : "=l"(d) : "l"(a), "l"(b), "l"(c)); return d;
}

// ---------------- cp.async helpers ----------------
__device__ __forceinline__ void cpa16(unsigned int dst, const void* src) {
    asm volatile("cp.async.ca.shared.global [%0], [%1], 16;" :: "r"(dst), "l"(src));
}
__device__ __forceinline__ void cpa_commit() {
    asm volatile("cp.async.commit_group;");
}
template <int N>
__device__ __forceinline__ void cpa_wait() {
    asm volatile("cp.async.wait_group %0;" :: "n"(N));
}

// ---------------- init: transpose codebook + reset counter ----------------
__global__ void vq_init(const float* __restrict__ emb) {
    int k = blockIdx.x * 64 + threadIdx.x;        // grid 16 x 64
    #pragma unroll
    for (int j = 0; j < DIM / 4; ++j) {
        float4 v;
        v.x = emb[(4 * j + 0) * KCODES + k];
        v.y = emb[(4 * j + 1) * KCODES + k];
        v.z = emb[(4 * j + 2) * KCODES + k];
        v.w = emb[(4 * j + 3) * KCODES + k];
        ((float4*)(g_cbT + (size_t)k * DIM))[j] = v;
    }
    if (blockIdx.x == 0 && threadIdx.x == 0) g_count = 0;
}

// ---------------- main ----------------
// dynamic smem (floats):
//   cbs : 2 x [DIM][KCHUNK]  double-buffered codebook chunk  16384 f (64 KB)
//   ses : [KCHUNK]                                             128 f
//   red : 128 doubles                                          256 f
#define CBS_OFF  0
#define SES_OFF  (2 * DIM * KCHUNK)
#define RED_OFF  (SES_OFF + KCHUNK)
#define SMEM_BYTES ((RED_OFF + 256) * 4)

__global__ void __launch_bounds__(THREADS, 3)
vq_main(const float* __restrict__ z,
        const float* __restrict__ emb,
        float* __restrict__ out)
{
    extern __shared__ float smem[];
    float*  cbs = smem + CBS_OFF;
    float*  ses = smem + SES_OFF;
    double* red = (double*)(smem + RED_OFF);
    __shared__ int s_last;

    const int b = blockIdx.x;
    const int t = threadIdx.x;
    const size_t row0 = (size_t)b * ROWS_CTA;

    // ---- prologue: prefetch chunks 0 and 1 via cp.async ----
    #pragma unroll
    for (int c = 0; c < 2; ++c) {
        #pragma unroll
        for (int i = 0; i < 16; ++i) {
            int idx = i * THREADS + t;                   // float4 index in chunk
            int d   = idx >> 5;                          // 32 float4 per d-row
            int kc4 = idx & 31;
            unsigned int dst = (unsigned int)__cvta_generic_to_shared(
                                   cbs + c * (DIM * KCHUNK) + 4 * idx);
            cpa16(dst, emb + (size_t)d * KCODES + c * KCHUNK + 4 * kc4);
        }
        cpa_commit();
    }

    // ---- load this thread's two z rows into registers ----
    float zr0[DIM], zr1[DIM];
    float sz0 = 0.0f, sz1 = 0.0f;
    {
        const float4* p0 = (const float4*)(z + (row0 + 2 * t)     * DIM);
        const float4* p1 = (const float4*)(z + (row0 + 2 * t + 1) * DIM);
        #pragma unroll
        for (int j = 0; j < DIM / 4; ++j) {
            float4 a = p0[j];
            zr0[4*j+0] = a.x; zr0[4*j+1] = a.y; zr0[4*j+2] = a.z; zr0[4*j+3] = a.w;
            float4 c = p1[j];
            zr1[4*j+0] = c.x; zr1[4*j+1] = c.y; zr1[4*j+2] = c.z; zr1[4*j+3] = c.w;
        }
        // s_z: square then add, ascending d (matches reference)
        #pragma unroll
        for (int d = 0; d < DIM; ++d) {
            sz0 = __fadd_rn(sz0, __fmul_rn(zr0[d], zr0[d]));
            sz1 = __fadd_rn(sz1, __fmul_rn(zr1[d], zr1[d]));
        }
    }

    float best0 = CUDART_INF_F, best1 = CUDART_INF_F;
    int   bi0 = 0, bi1 = 0;

    #pragma unroll 1
    for (int c = 0; c < NCHUNK; ++c) {
        // wait for chunk c (at most one newer group — chunk c+1 — may remain)
        if (c + 1 < NCHUNK) cpa_wait<1>(); else cpa_wait<0>();
        __syncthreads();

        float* cur = cbs + (c & 1) * (DIM * KCHUNK);

        // per-code squared norms from the staged chunk: sequential ascending d
        {
            float s = 0.0f;
            #pragma unroll
            for (int d = 0; d < DIM; ++d) {
                float v = cur[d * KCHUNK + t];
                s = __fadd_rn(s, __fmul_rn(v, v));
            }
            ses[t] = s;
        }
        __syncthreads();

        {
            const ulonglong2* cb2 = (const ulonglong2*)cur;   // 32 per d-row
            const int         k0  = c * KCHUNK;

            #pragma unroll 1                     // keep hot loop I$-resident
            for (int kg = 0; kg < KCHUNK; kg += 8) {
                const ulonglong2* cbk = cb2 + (kg >> 2);
                // aF[q]: (z0,z1) x (e_{2q},e_{2q+1}); aS[q]: (z1,z0) x same
                u64 aF[4] = {0,0,0,0}, aS[4] = {0,0,0,0};
                #pragma unroll
                for (int d = 0; d < DIM; ++d) {
                    ulonglong2 e01 = cbk[d * 32];        // codes kg..kg+3 (broadcast)
                    ulonglong2 e23 = cbk[d * 32 + 1];    // codes kg+4..kg+7
                    u64 zzA = pk2(zr0[d], zr1[d]);
                    u64 zzB = pk2(zr1[d], zr0[d]);
                    aF[0] = ffma2(zzA, e01.x, aF[0]);  aS[0] = ffma2(zzB, e01.x, aS[0]);
                    aF[1] = ffma2(zzA, e01.y, aF[1]);  aS[1] = ffma2(zzB, e01.y, aS[1]);
                    aF[2] = ffma2(zzA, e23.x, aF[2]);  aS[2] = ffma2(zzB, e23.x, aS[2]);
                    aF[3] = ffma2(zzA, e23.y, aF[3]);  aS[3] = ffma2(zzB, e23.y, aS[3]);
                }
                // scalar distance epilogue: (sz - 2*dot) + se  (exact fp32)
                #pragma unroll
                for (int q = 0; q < 4; ++q) {
                    float2 fab = u2f2(aF[q]);
                    float2 sab = u2f2(aS[q]);
                    int   kE = k0 + kg + 2 * q, kO = kE + 1;
                    float seE = ses[kg + 2 * q];
                    float seO = ses[kg + 2 * q + 1];
                    // ascending code order per row, strict < => first occurrence
                    float dE0 = __fadd_rn(__fsub_rn(sz0, __fmul_rn(2.0f, fab.x)), seE);
                    float dO0 = __fadd_rn(__fsub_rn(sz0, __fmul_rn(2.0f, sab.y)), seO);
                    float dE1 = __fadd_rn(__fsub_rn(sz1, __fmul_rn(2.0f, sab.x)), seE);
                    float dO1 = __fadd_rn(__fsub_rn(sz1, __fmul_rn(2.0f, fab.y)), seO);
                    if (dE0 < best0) { best0 = dE0; bi0 = kE; }
                    if (dO0 < best0) { best0 = dO0; bi0 = kO; }
                    if (dE1 < best1) { best1 = dE1; bi1 = kE; }
                    if (dO1 < best1) { best1 = dO1; bi1 = kO; }
                }
            }
        }
        __syncthreads();

        // prefetch chunk c+2 into the buffer we just finished with
        if (c + 2 < NCHUNK) {
            #pragma unroll
            for (int i = 0; i < 16; ++i) {
                int idx = i * THREADS + t;
                int d   = idx >> 5;
                int kc4 = idx & 31;
                unsigned int dst = (unsigned int)__cvta_generic_to_shared(
                                       cbs + (c & 1) * (DIM * KCHUNK) + 4 * idx);
                cpa16(dst, emb + (size_t)d * KCODES + (c + 2) * KCHUNK + 4 * kc4);
            }
            cpa_commit();
        }
    }

    // ---- gather chosen codes from transposed codebook (contiguous),
    //      straight-through output, loss partial ----
    double lsum = 0.0;
    {
        const float4* qa = (const float4*)(g_cbT + (size_t)bi0 * DIM);
        const float4* qb = (const float4*)(g_cbT + (size_t)bi1 * DIM);
        float4* oa = (float4*)(out + (row0 + 2 * t)     * DIM);
        float4* ob = (float4*)(out + (row0 + 2 * t + 1) * DIM);
        #pragma unroll
        for (int j = 0; j < DIM / 4; ++j) {
            float4 q4a = qa[j], q4b = qb[j];
            float4 va, vb;
            #pragma unroll
            for (int cc = 0; cc < 4; ++cc) {
                int d = 4 * j + cc;
                float ea = __fsub_rn((&q4a.x)[cc], zr0[d]);
                float eb = __fsub_rn((&q4b.x)[cc], zr1[d]);
                (&va.x)[cc] = __fadd_rn(zr0[d], ea);
                (&vb.x)[cc] = __fadd_rn(zr1[d], eb);
                lsum += (double)__fmul_rn(ea, ea) + (double)__fmul_rn(eb, eb);
            }
            oa[j] = va;  ob[j] = vb;
        }
    }

    // deterministic CTA reduction (4 warps)
    #pragma unroll
    for (int o = 16; o > 0; o >>= 1)
        lsum += __shfl_down_sync(0xffffffffu, lsum, o);
    if ((t & 31) == 0) red[t >> 5] = lsum;
    __syncthreads();
    if (t == 0) {
        g_partials[b] = red[0] + red[1] + red[2] + red[3];
        __threadfence();
        unsigned v = atomicAdd(&g_count, 1);
        s_last = (v == NBLOCKS - 1) ? 1 : 0;
    }
    __syncthreads();

    // last CTA: fixed-order reduction of all partials -> vq_loss
    if (s_last) {
        __threadfence();
        double s = 0.0;
        #pragma unroll
        for (int i = 0; i < NBLOCKS / THREADS; ++i)      // 4 each, fixed order
            s += __ldcg(&g_partials[t * (NBLOCKS / THREADS) + i]);
        red[t] = s;
        __syncthreads();
        #pragma unroll
        for (int stp = 64; stp > 0; stp >>= 1) {
            if (t < stp) red[t] += red[t + stp];
            __syncthreads();
        }
        if (t == 0) {
            float L = (float)(red[0] / (double)(N_ROWS * DIM));
            // vq_loss = embedding_loss + 0.25 * commitment_loss (numerically equal)
            out[N_ROWS * DIM] = __fadd_rn(L, __fmul_rn(0.25f, L));
        }
    }
}

extern "C" void kernel_launch(void* const* d_in, const int* in_sizes, int n_in,
                              void* d_out, int out_size) {
    const float* z   = (const float*)d_in[0];
    const float* emb = (const float*)d_in[1];
    float* out = (float*)d_out;

    (void)in_sizes; (void)n_in; (void)out_size;

    cudaFuncSetAttribute(vq_main, cudaFuncAttributeMaxDynamicSharedMemorySize, SMEM_BYTES);

    vq_init<<<KCODES / 64, 64>>>(emb);
    vq_main<<<NBLOCKS, THREADS, SMEM_BYTES>>>(z, emb, out);
}